// round 3
// baseline (speedup 1.0000x reference)
#include <cuda_runtime.h>
#include <math.h>

#define BATCH   2048
#define NCH     128
#define TOTDIM  200

// Constant Wigner change-of-basis matrices A(l), computed on device each launch
// (deterministic, tiny). Only the leading (2l+1)x(2l+1) block of each is used.
__device__ float g_A[5][9][9];

// ---------------------------------------------------------------------------
// Init kernel: reproduce the Python _A(l) construction in fp64.
// ---------------------------------------------------------------------------
struct cplx { double re, im; };
__device__ __forceinline__ cplx cmul(cplx a, cplx b) {
    return { a.re * b.re - a.im * b.im, a.re * b.im + a.im * b.re };
}
__device__ __forceinline__ cplx cconj(cplx a) { return { a.re, -a.im }; }

__device__ __forceinline__ double dfact(int n) {
    double r = 1.0;
    for (int k = 2; k <= n; ++k) r *= (double)k;
    return r;
}
__device__ __forceinline__ double ipowd(double x, int n) {
    double r = 1.0;
    for (int i = 0; i < n; ++i) r *= x;
    return r;
}

// exp(i * k * pi/2) for integer k (handles negatives via two's-complement &3)
__device__ __forceinline__ cplx expi_halfpi(int k) {
    switch (k & 3) {
        case 0:  return {  1.0,  0.0 };
        case 1:  return {  0.0,  1.0 };
        case 2:  return { -1.0,  0.0 };
        default: return {  0.0, -1.0 };
    }
}

// small Wigner d-matrix entry for beta = -pi/2  (row mp, col m)
__device__ double small_d_entry(int l, int mp, int m) {
    const double cb =  0.70710678118654752440;  // cos(-pi/4)
    const double sb = -0.70710678118654752440;  // sin(-pi/4)
    double pref = sqrt(dfact(l + mp) * dfact(l - mp) * dfact(l + m) * dfact(l - m));
    double tot = 0.0;
    int s0 = max(0, m - mp);
    int s1 = min(l + m, l - mp);
    for (int s = s0; s <= s1; ++s) {
        double den = dfact(l + m - s) * dfact(s) * dfact(mp - m + s) * dfact(l - mp - s);
        double sgn = ((mp - m + s) & 1) ? -1.0 : 1.0;
        tot += sgn / den * ipowd(cb, 2 * l + m - mp - 2 * s) * ipowd(sb, mp - m + 2 * s);
    }
    return pref * tot;
}

// U(l) entry (sparse: 2 nonzeros per row)
__device__ cplx U_entry(int l, int row, int col) {
    const double is2 = 0.70710678118654752440;  // 1/sqrt(2)
    int mr = row - l, mc = col - l;
    if (mr == 0) return (mc == 0) ? cplx{ 1.0, 0.0 } : cplx{ 0.0, 0.0 };
    if (mr > 0) {
        if (mc ==  mr) return cplx{ ((mr & 1) ? -is2 : is2), 0.0 };  // (-1)^m/sqrt2
        if (mc == -mr) return cplx{ is2, 0.0 };                      // 1/sqrt2
        return { 0.0, 0.0 };
    }
    int m = -mr;
    if (mc == -m) return cplx{ 0.0, is2 };                      // i/sqrt2
    if (mc ==  m) return cplx{ 0.0, ((m & 1) ? is2 : -is2) };   // -i*(-1)^m/sqrt2
    return { 0.0, 0.0 };
}

__global__ void wigner_init_kernel() {
    int t = threadIdx.x;
    int base = 0;
    for (int l = 0; l < 5; ++l) {
        int d = 2 * l + 1, dd = d * d;
        if (t >= base && t < base + dd) {
            int e = t - base;
            int i = e / d, j = e % d;
            int ri = d - 1 - i, rj = d - 1 - j;
            // A[i][j] = Re( sum_{p,q} U[i,p] * Dc[p,q] * conj(U[j,q]) )
            // U row i is nonzero only at cols {i, rev(i)}.
            int ps[2] = { i, ri };  int np = (ri == i) ? 1 : 2;
            int qs[2] = { j, rj };  int nq = (rj == j) ? 1 : 2;
            double acc = 0.0;
            for (int pi = 0; pi < np; ++pi) {
                int p = ps[pi];
                cplx uip = U_entry(l, i, p);
                if (uip.re == 0.0 && uip.im == 0.0) continue;
                for (int qi = 0; qi < nq; ++qi) {
                    int q = qs[qi];
                    cplx ujq = U_entry(l, j, q);
                    if (ujq.re == 0.0 && ujq.im == 0.0) continue;
                    double sd = small_d_entry(l, p - l, q - l);
                    // Dc[p,q] = exp(-i*mu_p*a) * sd * exp(-i*mu_q*g),  a=-pi/2, g=pi/2
                    cplx dc = expi_halfpi(p - l);            // exp(+i*mu_p*pi/2)
                    dc = cmul(dc, cplx{ sd, 0.0 });
                    dc = cmul(dc, expi_halfpi(-(q - l)));    // exp(-i*mu_q*pi/2)
                    cplx term = cmul(cmul(uip, dc), cconj(ujq));
                    acc += term.re;
                }
            }
            g_A[l][i][j] = (float)acc;
        }
        base += dd;
    }
}

// ---------------------------------------------------------------------------
// Main kernel: per (batch, l) block, build D = Za * A * Zb * A^T * Zg in SMEM,
// then apply it along the d-axis for all 8 multiplicities, float4 on channels.
// ---------------------------------------------------------------------------
__device__ __forceinline__ float zc(const float* sc, int grp, int k, int L) {
    int am = (k >= L) ? (k - L) : (L - k);
    return sc[grp * 10 + am * 2 + 1];           // [..., 1] = cos
}
__device__ __forceinline__ float zs(const float* sc, int grp, int k, int L) {
    int mm = k - L;
    if (mm > 0) return  sc[grp * 10 + mm * 2];  // [..., 0] = sin
    if (mm < 0) return -sc[grp * 10 - mm * 2];
    return 0.0f;
}

template <int L>
__device__ __forceinline__ void process_l(const float* __restrict__ x,
                                          float* __restrict__ y,
                                          const float* __restrict__ al,
                                          const float* __restrict__ be,
                                          const float* __restrict__ ga,
                                          int b) {
    constexpr int D = 2 * L + 1;
    constexpr int OFFS[5] = { 0, 8, 32, 72, 128 };
    constexpr int OFF = OFFS[L];

    __shared__ float sc[30];       // [alpha|beta|gamma][m=0..4][sin,cos]
    __shared__ float As[D * D];    // A(l)
    __shared__ float T2[D * D];    // Zb * A^T * Zg
    __shared__ float Dm[D * D];    // final D

    const int tid = threadIdx.x;

    // Stage 0: stage sincos + A into shared
    if (tid < 10)       sc[tid] = al[b * 10 + tid];
    else if (tid < 20)  sc[tid] = be[b * 10 + (tid - 10)];
    else if (tid < 30)  sc[tid] = ga[b * 10 + (tid - 20)];
    if (tid >= 64 && tid < 64 + D * D) {
        int t = tid - 64;
        As[t] = g_A[L][t / D][t % D];
    }
    __syncthreads();

    // Stage 1: T2 = Zb * (A^T * Zg)
    if (tid < D * D) {
        const int i = tid / D, j = tid % D;
        const int ri = D - 1 - i, rj = D - 1 - j;
        float cg = zc(sc, 2, j, L);
        float sg = zs(sc, 2, rj, L);
        // A^T[i][j] = As[j*D+i]
        float t1a = As[j * D + i]  * cg + As[rj * D + i]  * sg;  // T1[i][j]
        float t1b = As[j * D + ri] * cg + As[rj * D + ri] * sg;  // T1[ri][j]
        T2[tid] = zc(sc, 1, i, L) * t1a + zs(sc, 1, i, L) * t1b;
    }
    __syncthreads();

    // Stage 2: D = Za * (A * T2)
    if (tid < D * D) {
        const int i = tid / D, j = tid % D;
        const int ri = D - 1 - i;
        float t3 = 0.0f, t3r = 0.0f;
#pragma unroll
        for (int k = 0; k < D; ++k) {
            float v = T2[k * D + j];
            t3  = fmaf(As[i * D + k],  v, t3);
            t3r = fmaf(As[ri * D + k], v, t3r);
        }
        Dm[tid] = zc(sc, 0, i, L) * t3 + zs(sc, 0, i, L) * t3r;
    }
    __syncthreads();

    // Stage 3: apply D along d-axis. 8 mults x 32 float4-lanes = 256 threads.
    const int mult = tid >> 5;
    const int lane = tid & 31;
    const size_t base = ((size_t)b * TOTDIM + OFF + mult * D) * NCH;
    const float4* xp = (const float4*)(x + base);
    float4* yp = (float4*)(y + base);

    float4 xr[D];
#pragma unroll
    for (int j = 0; j < D; ++j) xr[j] = xp[j * 32 + lane];

#pragma unroll
    for (int i = 0; i < D; ++i) {
        float4 acc = { 0.f, 0.f, 0.f, 0.f };
#pragma unroll
        for (int j = 0; j < D; ++j) {
            float c = Dm[i * D + j];
            acc.x = fmaf(c, xr[j].x, acc.x);
            acc.y = fmaf(c, xr[j].y, acc.y);
            acc.z = fmaf(c, xr[j].z, acc.z);
            acc.w = fmaf(c, xr[j].w, acc.w);
        }
        yp[i * 32 + lane] = acc;
    }
}

__global__ void __launch_bounds__(256)
wigner_main_kernel(const float* __restrict__ x,
                   const float* __restrict__ al,
                   const float* __restrict__ be,
                   const float* __restrict__ ga,
                   float* __restrict__ y) {
    int b = blockIdx.x;
    switch (blockIdx.y) {
        case 0:  process_l<0>(x, y, al, be, ga, b); break;
        case 1:  process_l<1>(x, y, al, be, ga, b); break;
        case 2:  process_l<2>(x, y, al, be, ga, b); break;
        case 3:  process_l<3>(x, y, al, be, ga, b); break;
        default: process_l<4>(x, y, al, be, ga, b); break;
    }
}

extern "C" void kernel_launch(void* const* d_in, const int* in_sizes, int n_in,
                              void* d_out, int out_size) {
    (void)in_sizes; (void)n_in; (void)out_size;
    const float* x  = (const float*)d_in[0];  // (2048, 200, 128) f32
    const float* al = (const float*)d_in[1];  // (2048, 5, 2) f32
    const float* be = (const float*)d_in[2];
    const float* ga = (const float*)d_in[3];
    float* y = (float*)d_out;

    wigner_init_kernel<<<1, 256>>>();
    dim3 grid(BATCH, 5);
    wigner_main_kernel<<<grid, 256>>>(x, al, be, ga, y);
}

// round 4
// speedup vs baseline: 2.3890x; 2.3890x over previous
#include <cuda_runtime.h>
#include <math.h>

#define BATCH   2048
#define NCH     128
#define TOTDIM  200

// Flattened offsets of the per-l D/A blocks: sizes 1,9,25,49,81 -> total 165
#define AOFF0 0
#define AOFF1 1
#define AOFF2 10
#define AOFF3 35
#define AOFF4 84
#define ATOT  165

struct AParams { float A[ATOT]; };   // constant Wigner A(l) blocks, passed by value

// Per-batch composed rotation matrices D(b,l), built by build_D_kernel.
__device__ float g_D[BATCH][ATOT];

// ---------------------------------------------------------------------------
// Host-side computation of the constant A(l) matrices (exact port of the
// Python reference, fp64). Runs at capture time only — zero replay cost.
// ---------------------------------------------------------------------------
static double h_fact(int n) {
    double r = 1.0;
    for (int k = 2; k <= n; ++k) r *= (double)k;
    return r;
}

static void host_compute_A(AParams& P) {
    const double PI = 3.14159265358979323846;
    const double IS2 = 0.70710678118654752440;
    int off = 0;
    for (int l = 0; l < 5; ++l) {
        int d = 2 * l + 1;
        // small Wigner d at beta = -pi/2
        double sd[9][9];
        double cb = cos(-PI / 4.0), sb = sin(-PI / 4.0);
        for (int mp = -l; mp <= l; ++mp) {
            for (int m = -l; m <= l; ++m) {
                double pref = sqrt(h_fact(l + mp) * h_fact(l - mp) *
                                   h_fact(l + m) * h_fact(l - m));
                double tot = 0.0;
                int s0 = (m - mp > 0) ? (m - mp) : 0;
                int s1 = (l + m < l - mp) ? (l + m) : (l - mp);
                for (int s = s0; s <= s1; ++s) {
                    double den = h_fact(l + m - s) * h_fact(s) *
                                 h_fact(mp - m + s) * h_fact(l - mp - s);
                    double sgn = ((mp - m + s) & 1) ? -1.0 : 1.0;
                    tot += sgn / den * pow(cb, 2 * l + m - mp - 2 * s)
                                     * pow(sb, mp - m + 2 * s);
                }
                sd[mp + l][m + l] = pref * tot;
            }
        }
        // Dc[p][q] = exp(-i*mu_p*a) * sd * exp(-i*mu_q*g), a=-pi/2, g=+pi/2
        double DcRe[9][9], DcIm[9][9];
        for (int p = 0; p < d; ++p) {
            for (int q = 0; q < d; ++q) {
                double ang = (p - l) * (PI / 2.0) - (q - l) * (PI / 2.0);
                DcRe[p][q] = cos(ang) * sd[p][q];
                DcIm[p][q] = sin(ang) * sd[p][q];
            }
        }
        // U
        double URe[9][9] = {}, UIm[9][9] = {};
        URe[l][l] = 1.0;
        for (int m = 1; m <= l; ++m) {
            double sgn = (m & 1) ? -1.0 : 1.0;
            URe[l + m][l + m] = sgn * IS2;
            URe[l + m][l - m] = IS2;
            UIm[l - m][l - m] = IS2;
            UIm[l - m][l + m] = -sgn * IS2;
        }
        // T = U * Dc
        double TRe[9][9], TIm[9][9];
        for (int i = 0; i < d; ++i) {
            for (int q = 0; q < d; ++q) {
                double re = 0.0, im = 0.0;
                for (int p = 0; p < d; ++p) {
                    re += URe[i][p] * DcRe[p][q] - UIm[i][p] * DcIm[p][q];
                    im += URe[i][p] * DcIm[p][q] + UIm[i][p] * DcRe[p][q];
                }
                TRe[i][q] = re; TIm[i][q] = im;
            }
        }
        // A[i][j] = Re( sum_q T[i][q] * conj(U[j][q]) )
        for (int i = 0; i < d; ++i) {
            for (int j = 0; j < d; ++j) {
                double a = 0.0;
                for (int q = 0; q < d; ++q)
                    a += TRe[i][q] * URe[j][q] + TIm[i][q] * UIm[j][q];
                P.A[off + i * d + j] = (float)a;
            }
        }
        off += d * d;
    }
}

// ---------------------------------------------------------------------------
// Z-rotation coefficient helpers (sc layout: grp(0=a,1=b,2=g)*10 + m*2 + {sin,cos})
// ---------------------------------------------------------------------------
__device__ __forceinline__ float zc(const float* sc, int grp, int k, int L) {
    int am = (k >= L) ? (k - L) : (L - k);
    return sc[grp * 10 + am * 2 + 1];
}
__device__ __forceinline__ float zs(const float* sc, int grp, int k, int L) {
    int mm = k - L;
    if (mm > 0) return  sc[grp * 10 + mm * 2];
    if (mm < 0) return -sc[grp * 10 - mm * 2];
    return 0.0f;
}

// ---------------------------------------------------------------------------
// Kernel 1: per batch b, build D(b,l) = Za * A * Zb * A^T * Zg for all l
// into g_D. 2048 blocks x 192 threads; tiny.
// ---------------------------------------------------------------------------
__global__ void __launch_bounds__(192)
build_D_kernel(AParams Ap,
               const float* __restrict__ al,
               const float* __restrict__ be,
               const float* __restrict__ ga) {
    const int b = blockIdx.x;
    const int tid = threadIdx.x;

    __shared__ float sc[30];
    __shared__ float T2[ATOT];

    if (tid < 10)       sc[tid] = al[b * 10 + tid];
    else if (tid < 20)  sc[tid] = be[b * 10 + (tid - 10)];
    else if (tid < 30)  sc[tid] = ga[b * 10 + (tid - 20)];
    __syncthreads();

    int l = 0, off = 0, D = 1;
    if (tid < ATOT) {
        if (tid >= AOFF4)      { l = 4; off = AOFF4; }
        else if (tid >= AOFF3) { l = 3; off = AOFF3; }
        else if (tid >= AOFF2) { l = 2; off = AOFF2; }
        else if (tid >= AOFF1) { l = 1; off = AOFF1; }
        D = 2 * l + 1;
    }
    const int e = tid - off;
    const int i = e / D, j = e - i * D;
    const int ri = D - 1 - i, rj = D - 1 - j;

    // Stage 1: T2 = Zb * (A^T * Zg)
    if (tid < ATOT) {
        float cg = zc(sc, 2, j, l);
        float sg = zs(sc, 2, rj, l);
        float t1a = Ap.A[off + j * D + i]  * cg + Ap.A[off + rj * D + i]  * sg;
        float t1b = Ap.A[off + j * D + ri] * cg + Ap.A[off + rj * D + ri] * sg;
        T2[tid] = zc(sc, 1, i, l) * t1a + zs(sc, 1, i, l) * t1b;
    }
    __syncthreads();

    // Stage 2: D = Za * (A * T2)
    if (tid < ATOT) {
        float t3 = 0.0f, t3r = 0.0f;
        for (int k = 0; k < D; ++k) {
            float v = T2[off + k * D + j];
            t3  = fmaf(Ap.A[off + i * D + k],  v, t3);
            t3r = fmaf(Ap.A[off + ri * D + k], v, t3r);
        }
        g_D[b][tid] = zc(sc, 0, i, l) * t3 + zs(sc, 0, i, l) * t3r;
    }
}

// ---------------------------------------------------------------------------
// Kernel 2: pure streaming apply. Each thread owns (mult, float4-lane),
// loads the segment's D rows of input once, produces all D outputs.
// Grid (2048, 4): y=0 -> l0+l1, y=1 -> l2, y=2 -> l3, y=3 -> l4.
// ---------------------------------------------------------------------------
template <int L>
__device__ __forceinline__ void apply_seg(const float* __restrict__ x,
                                          float* __restrict__ y,
                                          const float* Dm,  // smem, D*D
                                          int b, int OFF, int mult, int lane) {
    constexpr int D = 2 * L + 1;
    const size_t base = ((size_t)b * TOTDIM + OFF + mult * D) * NCH;
    const float4* xp = (const float4*)(x + base);
    float4* yp = (float4*)(y + base);

    float4 xr[D];
#pragma unroll
    for (int j = 0; j < D; ++j) xr[j] = xp[j * 32 + lane];

#pragma unroll
    for (int i = 0; i < D; ++i) {
        float4 acc = { 0.f, 0.f, 0.f, 0.f };
#pragma unroll
        for (int j = 0; j < D; ++j) {
            float c = Dm[i * D + j];
            acc.x = fmaf(c, xr[j].x, acc.x);
            acc.y = fmaf(c, xr[j].y, acc.y);
            acc.z = fmaf(c, xr[j].z, acc.z);
            acc.w = fmaf(c, xr[j].w, acc.w);
        }
        yp[i * 32 + lane] = acc;
    }
}

__global__ void __launch_bounds__(256)
apply_kernel(const float* __restrict__ x, float* __restrict__ y) {
    const int b = blockIdx.x;
    const int tid = threadIdx.x;
    const int mult = tid >> 5;
    const int lane = tid & 31;

    __shared__ float DmS[81];
    const float* Db = g_D[b];

    switch (blockIdx.y) {
        case 0: {  // l=0 (rows 0..7) + l=1 (rows 8..31); D blocks at [0] and [1..9]
            if (tid < 10) DmS[tid] = Db[tid];
            __syncthreads();
            {   // l=0: identity-sized 1x1
                const size_t base = ((size_t)b * TOTDIM + mult) * NCH;
                const float4* xp = (const float4*)(x + base);
                float4* yp = (float4*)(y + base);
                float c = DmS[0];
                float4 v = xp[lane];
                yp[lane] = { c * v.x, c * v.y, c * v.z, c * v.w };
            }
            apply_seg<1>(x, y, DmS + 1, b, 8, mult, lane);
            break;
        }
        case 1: {
            if (tid < 25) DmS[tid] = Db[AOFF2 + tid];
            __syncthreads();
            apply_seg<2>(x, y, DmS, b, 32, mult, lane);
            break;
        }
        case 2: {
            if (tid < 49) DmS[tid] = Db[AOFF3 + tid];
            __syncthreads();
            apply_seg<3>(x, y, DmS, b, 72, mult, lane);
            break;
        }
        default: {
            if (tid < 81) DmS[tid] = Db[AOFF4 + tid];
            __syncthreads();
            apply_seg<4>(x, y, DmS, b, 128, mult, lane);
            break;
        }
    }
}

// ---------------------------------------------------------------------------
extern "C" void kernel_launch(void* const* d_in, const int* in_sizes, int n_in,
                              void* d_out, int out_size) {
    (void)in_sizes; (void)n_in; (void)out_size;
    const float* x  = (const float*)d_in[0];  // (2048, 200, 128) f32
    const float* al = (const float*)d_in[1];  // (2048, 5, 2) f32
    const float* be = (const float*)d_in[2];
    const float* ga = (const float*)d_in[3];
    float* y = (float*)d_out;

    AParams P;
    host_compute_A(P);   // host-side, capture-time only

    build_D_kernel<<<BATCH, 192>>>(P, al, be, ga);
    dim3 grid(BATCH, 4);
    apply_kernel<<<grid, 256>>>(x, y);
}

// round 9
// speedup vs baseline: 2.7846x; 1.1656x over previous
#include <cuda_runtime.h>
#include <math.h>

#define BATCH   2048
#define NCH     128
#define TOTDIM  200

// Flattened offsets of the per-l A blocks: sizes 1,9,25,49,81 -> total 165
#define AOFF0 0
#define AOFF1 1
#define AOFF2 10
#define AOFF3 35
#define AOFF4 84
#define ATOT  165

struct AParams { float A[ATOT]; };   // constant Wigner A(l) blocks

// ---------------------------------------------------------------------------
// Host-side computation of the constant A(l) matrices (exact port of the
// Python reference, fp64). Runs at capture time only — zero replay cost.
// ---------------------------------------------------------------------------
static double h_fact(int n) {
    double r = 1.0;
    for (int k = 2; k <= n; ++k) r *= (double)k;
    return r;
}

static void host_compute_A(AParams& P) {
    const double PI = 3.14159265358979323846;
    const double IS2 = 0.70710678118654752440;
    int off = 0;
    for (int l = 0; l < 5; ++l) {
        int d = 2 * l + 1;
        double sd[9][9];
        double cb = cos(-PI / 4.0), sb = sin(-PI / 4.0);
        for (int mp = -l; mp <= l; ++mp) {
            for (int m = -l; m <= l; ++m) {
                double pref = sqrt(h_fact(l + mp) * h_fact(l - mp) *
                                   h_fact(l + m) * h_fact(l - m));
                double tot = 0.0;
                int s0 = (m - mp > 0) ? (m - mp) : 0;
                int s1 = (l + m < l - mp) ? (l + m) : (l - mp);
                for (int s = s0; s <= s1; ++s) {
                    double den = h_fact(l + m - s) * h_fact(s) *
                                 h_fact(mp - m + s) * h_fact(l - mp - s);
                    double sgn = ((mp - m + s) & 1) ? -1.0 : 1.0;
                    tot += sgn / den * pow(cb, 2 * l + m - mp - 2 * s)
                                     * pow(sb, mp - m + 2 * s);
                }
                sd[mp + l][m + l] = pref * tot;
            }
        }
        double DcRe[9][9], DcIm[9][9];
        for (int p = 0; p < d; ++p) {
            for (int q = 0; q < d; ++q) {
                double ang = (p - l) * (PI / 2.0) - (q - l) * (PI / 2.0);
                DcRe[p][q] = cos(ang) * sd[p][q];
                DcIm[p][q] = sin(ang) * sd[p][q];
            }
        }
        double URe[9][9] = {}, UIm[9][9] = {};
        URe[l][l] = 1.0;
        for (int m = 1; m <= l; ++m) {
            double sgn = (m & 1) ? -1.0 : 1.0;
            URe[l + m][l + m] = sgn * IS2;
            URe[l + m][l - m] = IS2;
            UIm[l - m][l - m] = IS2;
            UIm[l - m][l + m] = -sgn * IS2;
        }
        double TRe[9][9], TIm[9][9];
        for (int i = 0; i < d; ++i) {
            for (int q = 0; q < d; ++q) {
                double re = 0.0, im = 0.0;
                for (int p = 0; p < d; ++p) {
                    re += URe[i][p] * DcRe[p][q] - UIm[i][p] * DcIm[p][q];
                    im += URe[i][p] * DcIm[p][q] + UIm[i][p] * DcRe[p][q];
                }
                TRe[i][q] = re; TIm[i][q] = im;
            }
        }
        for (int i = 0; i < d; ++i) {
            for (int j = 0; j < d; ++j) {
                double a = 0.0;
                for (int q = 0; q < d; ++q)
                    a += TRe[i][q] * URe[j][q] + TIm[i][q] * UIm[j][q];
                P.A[off + i * d + j] = (float)a;
            }
        }
        off += d * d;
    }
}

// ---------------------------------------------------------------------------
// Z-rotation coefficient helpers (sc layout: grp(0=a,1=b,2=g)*10 + m*2 + {sin,cos})
// ---------------------------------------------------------------------------
__device__ __forceinline__ float zc(const float* sc, int grp, int k, int L) {
    int am = (k >= L) ? (k - L) : (L - k);
    return sc[grp * 10 + am * 2 + 1];
}
__device__ __forceinline__ float zs(const float* sc, int grp, int k, int L) {
    int mm = k - L;
    if (mm > 0) return  sc[grp * 10 + mm * 2];
    if (mm < 0) return -sc[grp * 10 - mm * 2];
    return 0.0f;
}

// Single-stage closed-form for one entry of D = Za * A * Zb * A^T * Zg.
// A is the l-block (D x D) staged in shared memory.
template <int L>
__device__ __forceinline__ float build_entry(const float* sc, const float* A, int e) {
    constexpr int D = 2 * L + 1;
    const int i = e / D, j = e - i * D;
    const int ri = D - 1 - i, rj = D - 1 - j;
    const float cg = zc(sc, 2, j, L);
    const float sg = zs(sc, 2, rj, L);
    float t3 = 0.0f, t3r = 0.0f;
#pragma unroll
    for (int k = 0; k < D; ++k) {
        const int rk = D - 1 - k;
        // T1[k][j]  = A^T[k][j]*cg + A^T[k][rj]*sg  = A[j][k]*cg + A[rj][k]*sg
        float T1k  = A[j * D + k]  * cg + A[rj * D + k]  * sg;
        float T1rk = A[j * D + rk] * cg + A[rj * D + rk] * sg;
        // T2[k][j]  = cb(k)*T1[k][j] + sb(k)*T1[rk][j]
        float T2k = zc(sc, 1, k, L) * T1k + zs(sc, 1, k, L) * T1rk;
        t3  = fmaf(A[i * D + k],  T2k, t3);
        t3r = fmaf(A[ri * D + k], T2k, t3r);
    }
    return zc(sc, 0, i, L) * t3 + zs(sc, 0, i, L) * t3r;
}

// ---------------------------------------------------------------------------
// Fused kernel: per (batch, segment-class) block.
//   - pre-issue all x loads (stay in flight across barriers)
//   - stage sincos + A block into smem
//   - build D block in smem (one stage, <=81 threads)
//   - FMA + store
// Grid (2048, 4): y=0 -> l0+l1, y=1 -> l2, y=2 -> l3, y=3 -> l4.
// ---------------------------------------------------------------------------
template <int L>
__device__ __forceinline__ void seg_full(const float* __restrict__ x,
                                         float* __restrict__ y,
                                         const float* __restrict__ Ablk,
                                         float* sc, float* AsS, float* DmS,
                                         int b, int OFF, int tid) {
    constexpr int D = 2 * L + 1;
    const int mult = tid >> 5;
    const int lane = tid & 31;
    const size_t base = ((size_t)b * TOTDIM + OFF + mult * D) * NCH;
    const float4* xp = (const float4*)(x + base);
    float4* yp = (float4*)(y + base);

    // Pre-issue global loads — these overlap the D build below.
    float4 xr[D];
#pragma unroll
    for (int j = 0; j < D; ++j) xr[j] = xp[j * 32 + lane];

    // Stage A block (threads 64.. to avoid stacking on the sc-staging threads)
    if (tid >= 64 && tid < 64 + D * D) AsS[tid - 64] = Ablk[tid - 64];
    __syncthreads();

    if (tid < D * D) DmS[tid] = build_entry<L>(sc, AsS, tid);
    __syncthreads();

#pragma unroll
    for (int i = 0; i < D; ++i) {
        float4 acc = { 0.f, 0.f, 0.f, 0.f };
#pragma unroll
        for (int j = 0; j < D; ++j) {
            float c = DmS[i * D + j];
            acc.x = fmaf(c, xr[j].x, acc.x);
            acc.y = fmaf(c, xr[j].y, acc.y);
            acc.z = fmaf(c, xr[j].z, acc.z);
            acc.w = fmaf(c, xr[j].w, acc.w);
        }
        yp[i * 32 + lane] = acc;
    }
}

__global__ void __launch_bounds__(256)
fused_kernel(const AParams Ap,
             const float* __restrict__ x,
             const float* __restrict__ al,
             const float* __restrict__ be,
             const float* __restrict__ ga,
             float* __restrict__ y) {
    const int b = blockIdx.x;
    const int tid = threadIdx.x;

    __shared__ float sc[30];
    __shared__ float AsS[81];
    __shared__ float DmS[81];

    // Stage sincos (threads 0..29)
    if (tid < 10)       sc[tid] = al[b * 10 + tid];
    else if (tid < 20)  sc[tid] = be[b * 10 + (tid - 10)];
    else if (tid < 30)  sc[tid] = ga[b * 10 + (tid - 20)];

    switch (blockIdx.y) {
        case 0: {  // l=0 (rows 0..7) + l=1 (rows 8..31)
            const int mult = tid >> 5;
            const int lane = tid & 31;
            const size_t base0 = ((size_t)b * TOTDIM + mult) * NCH;
            const size_t base1 = ((size_t)b * TOTDIM + 8 + mult * 3) * NCH;
            const float4* xp0 = (const float4*)(x + base0);
            const float4* xp1 = (const float4*)(x + base1);

            float4 x0 = xp0[lane];
            float4 xr[3];
#pragma unroll
            for (int j = 0; j < 3; ++j) xr[j] = xp1[j * 32 + lane];

            if (tid >= 64 && tid < 64 + 10) AsS[tid - 64] = Ap.A[tid - 64];
            __syncthreads();

            if (tid == 0)            DmS[0]  = build_entry<0>(sc, AsS, 0);
            else if (tid < 10)       DmS[tid] = build_entry<1>(sc, AsS + 1, tid - 1);
            __syncthreads();

            {   // l=0
                float c = DmS[0];
                float4* yp0 = (float4*)(y + base0);
                yp0[lane] = { c * x0.x, c * x0.y, c * x0.z, c * x0.w };
            }
            {   // l=1
                float4* yp1 = (float4*)(y + base1);
#pragma unroll
                for (int i = 0; i < 3; ++i) {
                    float4 acc = { 0.f, 0.f, 0.f, 0.f };
#pragma unroll
                    for (int j = 0; j < 3; ++j) {
                        float c = DmS[1 + i * 3 + j];
                        acc.x = fmaf(c, xr[j].x, acc.x);
                        acc.y = fmaf(c, xr[j].y, acc.y);
                        acc.z = fmaf(c, xr[j].z, acc.z);
                        acc.w = fmaf(c, xr[j].w, acc.w);
                    }
                    yp1[i * 32 + lane] = acc;
                }
            }
            break;
        }
        case 1: seg_full<2>(x, y, Ap.A + AOFF2, sc, AsS, DmS, b, 32,  tid); break;
        case 2: seg_full<3>(x, y, Ap.A + AOFF3, sc, AsS, DmS, b, 72,  tid); break;
        default: seg_full<4>(x, y, Ap.A + AOFF4, sc, AsS, DmS, b, 128, tid); break;
    }
}

// ---------------------------------------------------------------------------
extern "C" void kernel_launch(void* const* d_in, const int* in_sizes, int n_in,
                              void* d_out, int out_size) {
    (void)in_sizes; (void)n_in; (void)out_size;
    const float* x  = (const float*)d_in[0];  // (2048, 200, 128) f32
    const float* al = (const float*)d_in[1];  // (2048, 5, 2) f32
    const float* be = (const float*)d_in[2];
    const float* ga = (const float*)d_in[3];
    float* y = (float*)d_out;

    AParams P;
    host_compute_A(P);   // host-side, capture-time only

    dim3 grid(BATCH, 4);
    fused_kernel<<<grid, 256>>>(P, x, al, be, ga, y);
}